// round 2
// baseline (speedup 1.0000x reference)
#include <cuda_runtime.h>

// Problem shape (fixed by reference): B=8, C=21, H=W=512.
#define NUM_C 21
#define HW    (512 * 512)       // 262144 elements per (b,c) slab
#define HW4   (HW / 4)          // 65536 float4s per slab
#define BLOCKS_PER_SLAB 16
#define THREADS 256
#define CHUNK4 (HW4 / BLOCKS_PER_SLAB)  // 4096 float4s per block

// Scratch counters: [inter | pred_sum | target_sum] x NUM_C
__device__ unsigned int g_cnt[3 * NUM_C];

__global__ void zero_kernel() {
    int i = threadIdx.x;
    if (i < 3 * NUM_C) g_cnt[i] = 0u;
}

__global__ __launch_bounds__(THREADS) void count_kernel(
    const float* __restrict__ preds,
    const float* __restrict__ target)
{
    const int slab = blockIdx.x / BLOCKS_PER_SLAB;   // 0 .. B*C-1
    const int sub  = blockIdx.x % BLOCKS_PER_SLAB;
    const int c    = slab % NUM_C;

    const float4* __restrict__ p4 =
        reinterpret_cast<const float4*>(preds)  + (long long)slab * HW4;
    const float4* __restrict__ t4 =
        reinterpret_cast<const float4*>(target) + (long long)slab * HW4;

    const int start = sub * CHUNK4;

    unsigned int cp = 0, ct = 0, ci = 0;

    #pragma unroll 8
    for (int j = start + threadIdx.x; j < start + CHUNK4; j += THREADS) {
        float4 p = p4[j];
        float4 t = t4[j];
        unsigned int px = p.x >= 0.5f, py = p.y >= 0.5f,
                     pz = p.z >= 0.5f, pw = p.w >= 0.5f;
        unsigned int tx = t.x == 1.0f, ty = t.y == 1.0f,
                     tz = t.z == 1.0f, tw = t.w == 1.0f;
        cp += px + py + pz + pw;
        ct += tx + ty + tz + tw;
        ci += (px & tx) + (py & ty) + (pz & tz) + (pw & tw);
    }

    // Warp reduce
    #pragma unroll
    for (int off = 16; off > 0; off >>= 1) {
        cp += __shfl_down_sync(0xFFFFFFFFu, cp, off);
        ct += __shfl_down_sync(0xFFFFFFFFu, ct, off);
        ci += __shfl_down_sync(0xFFFFFFFFu, ci, off);
    }

    // Block reduce via shared
    __shared__ unsigned int s_cp, s_ct, s_ci;
    if (threadIdx.x == 0) { s_cp = 0u; s_ct = 0u; s_ci = 0u; }
    __syncthreads();
    if ((threadIdx.x & 31) == 0) {
        atomicAdd(&s_cp, cp);
        atomicAdd(&s_ct, ct);
        atomicAdd(&s_ci, ci);
    }
    __syncthreads();
    if (threadIdx.x == 0) {
        atomicAdd(&g_cnt[c],              s_ci);  // inter
        atomicAdd(&g_cnt[NUM_C + c],      s_cp);  // pred_sum
        atomicAdd(&g_cnt[2 * NUM_C + c],  s_ct);  // target_sum
    }
}

__global__ void finalize_kernel(float* __restrict__ out) {
    int c = threadIdx.x;
    if (c < NUM_C) {
        float inter = (float)g_cnt[c];
        float psum  = (float)g_cnt[NUM_C + c];
        float tsum  = (float)g_cnt[2 * NUM_C + c];
        float uni   = psum + tsum - inter;
        out[c] = (uni == 0.0f) ? __int_as_float(0x7FC00000)   // NaN
                               : inter / fmaxf(uni, 1.0f);
    }
}

extern "C" void kernel_launch(void* const* d_in, const int* in_sizes, int n_in,
                              void* d_out, int out_size)
{
    const float* preds  = (const float*)d_in[0];
    const float* target = (const float*)d_in[1];
    float* out = (float*)d_out;

    const int slabs = in_sizes[0] / HW;  // B*C = 168 for the reference shape

    zero_kernel<<<1, 64>>>();
    count_kernel<<<slabs * BLOCKS_PER_SLAB, THREADS>>>(preds, target);
    finalize_kernel<<<1, 32>>>(out);
}